// round 15
// baseline (speedup 1.0000x reference)
#include <cuda_runtime.h>
#include <math.h>
#include <stdint.h>

// Problem constants
#define NROWS 8192
#define DD    1024
#define HH    4096
#define NL    5          // NUM_LAYERS + 1 blocks
#define BIGN  6144       // 5*1024 (out_i) + 1024 (inv_total)
#define OUTCOLS 5120
#define NCHUNK 32        // loss row chunks

// ---------------- scratch (static device memory; no allocations) -------------
__device__ float g_T1[(size_t)DD*HH];       // fc1_W^T  [1024,4096]
__device__ float g_T2[(size_t)HH*DD];       // fc2_W^T  [4096,1024]
__device__ float g_cT[(size_t)NL*DD*DD];    // comp_W[z]^T  [m][j]
__device__ float g_Qs[(size_t)NL*DD*DD];    // Q_1..Q_5 (Qs[0] = M)
__device__ float g_Nm[(size_t)DD*DD];       // running N
__device__ float g_Qsum[(size_t)DD*DD];
__device__ float g_dvec[NL*DD];             // d_1..d_5 (dvec[0] = c)
__device__ float g_fv[DD];
__device__ float g_dsum[DD];
__device__ float g_Wbig[(size_t)DD*BIGN];
__device__ float g_bias[BIGN];
__device__ float g_OUT[(size_t)NL*NROWS*DD];  // out_i matrices (168 MB)
__device__ float g_S[NL*NROWS];
__device__ float g_n2[NL*NROWS];
__device__ float g_Dpart[NL*NCHUNK*DD];
__device__ float g_Dv[DD];

// ---------------- transpose (tiled, dims are multiples of 32) ----------------
__global__ void transpose_k(const float* __restrict__ in, float* __restrict__ out,
                            int R, int C) {
    __shared__ float tile[32][33];
    const float* ip = in  + (size_t)blockIdx.z * R * C;
    float*       op = out + (size_t)blockIdx.z * R * C;
    int x  = blockIdx.x * 32 + threadIdx.x;
    int y0 = blockIdx.y * 32 + threadIdx.y;
#pragma unroll
    for (int k = 0; k < 32; k += 8)
        tile[threadIdx.y + k][threadIdx.x] = ip[(size_t)(y0 + k) * C + x];
    __syncthreads();
    int ox  = blockIdx.y * 32 + threadIdx.x;
    int oy0 = blockIdx.x * 32 + threadIdx.y;
#pragma unroll
    for (int k = 0; k < 32; k += 8)
        op[(size_t)(oy0 + k) * R + ox] = tile[threadIdx.x][threadIdx.y + k];
}

// ---------------- small NN GEMM: 64x64 tile, BK=16, 256 thr, 4x4/thread ------
__global__ __launch_bounds__(256)
void gemm64(const float* __restrict__ A, const float* __restrict__ B,
            float* __restrict__ C, int K, int lda, int ldb, int ldc,
            size_t sA, size_t sB, size_t sC) {
    A += (size_t)blockIdx.z * sA;
    B += (size_t)blockIdx.z * sB;
    C += (size_t)blockIdx.z * sC;
    __shared__ float As[16][68];
    __shared__ float Bs[16][64];
    int t  = threadIdx.x;
    int m0 = blockIdx.y * 64, n0 = blockIdx.x * 64;
    int am = t >> 2, ak = (t & 3) * 4;
    int bk = t >> 4, bn = (t & 15) * 4;
    int ty = t >> 4, tx = t & 15;
    float acc[4][4] = {};
    const float* Aload = A + (size_t)(m0 + am) * lda + ak;
    const float* Bload = B + (size_t)bk * ldb + n0 + bn;
    for (int k0 = 0; k0 < K; k0 += 16) {
        float4 a4 = *(const float4*)(Aload + k0);
        float4 b4 = *(const float4*)(Bload + (size_t)k0 * ldb);
        __syncthreads();
        As[ak + 0][am] = a4.x; As[ak + 1][am] = a4.y;
        As[ak + 2][am] = a4.z; As[ak + 3][am] = a4.w;
        *(float4*)&Bs[bk][bn] = b4;
        __syncthreads();
#pragma unroll
        for (int k = 0; k < 16; k++) {
            float4 av = *(const float4*)&As[k][ty * 4];
            float4 bv = *(const float4*)&Bs[k][tx * 4];
            float a[4] = {av.x, av.y, av.z, av.w};
            float b[4] = {bv.x, bv.y, bv.z, bv.w};
#pragma unroll
            for (int i = 0; i < 4; i++)
#pragma unroll
                for (int j = 0; j < 4; j++)
                    acc[i][j] += a[i] * b[j];
        }
    }
#pragma unroll
    for (int i = 0; i < 4; i++) {
        float4 v = make_float4(acc[i][0], acc[i][1], acc[i][2], acc[i][3]);
        *(float4*)&C[(size_t)(m0 + ty * 4 + i) * ldc + n0 + tx * 4] = v;
    }
}

// ---------------- big GEMM: C = x @ Wbig + bias, fused routed epilogue -------
// 128x128 tile, BK=16, 256 thr, 8x8/thread
__global__ __launch_bounds__(256, 2)
void gemm_big(const float* __restrict__ A, float* __restrict__ d_inv,
              float* __restrict__ d_nxt) {
    __shared__ float As[16][132];
    __shared__ float Bs[16][128];
    int t  = threadIdx.x;
    int m0 = blockIdx.y * 128, n0 = blockIdx.x * 128;
    int ty = t >> 4, tx = t & 15;
    float acc[8][8] = {};
    for (int k0 = 0; k0 < DD; k0 += 16) {
        int f0 = t, f1 = t + 256;
        float4 a0 = *(const float4*)&A[(size_t)(m0 + (f0 >> 2)) * DD + k0 + (f0 & 3) * 4];
        float4 a1 = *(const float4*)&A[(size_t)(m0 + (f1 >> 2)) * DD + k0 + (f1 & 3) * 4];
        float4 b0 = *(const float4*)&g_Wbig[(size_t)(k0 + (f0 >> 5)) * BIGN + n0 + (f0 & 31) * 4];
        float4 b1 = *(const float4*)&g_Wbig[(size_t)(k0 + (f1 >> 5)) * BIGN + n0 + (f1 & 31) * 4];
        __syncthreads();
        {
            int am = f0 >> 2, ak = (f0 & 3) * 4;
            As[ak][am] = a0.x; As[ak + 1][am] = a0.y; As[ak + 2][am] = a0.z; As[ak + 3][am] = a0.w;
            am = f1 >> 2; ak = (f1 & 3) * 4;
            As[ak][am] = a1.x; As[ak + 1][am] = a1.y; As[ak + 2][am] = a1.z; As[ak + 3][am] = a1.w;
            *(float4*)&Bs[f0 >> 5][(f0 & 31) * 4] = b0;
            *(float4*)&Bs[f1 >> 5][(f1 & 31) * 4] = b1;
        }
        __syncthreads();
#pragma unroll
        for (int k = 0; k < 16; k++) {
            float a[8], b[8];
            *(float4*)&a[0] = *(const float4*)&As[k][ty * 8];
            *(float4*)&a[4] = *(const float4*)&As[k][ty * 8 + 4];
            *(float4*)&b[0] = *(const float4*)&Bs[k][tx * 8];
            *(float4*)&b[4] = *(const float4*)&Bs[k][tx * 8 + 4];
#pragma unroll
            for (int i = 0; i < 8; i++)
#pragma unroll
                for (int j = 0; j < 8; j++)
                    acc[i][j] += a[i] * b[j];
        }
    }
    // routed epilogue
#pragma unroll
    for (int i = 0; i < 8; i++) {
        int row = m0 + ty * 8 + i;
#pragma unroll
        for (int j = 0; j < 8; j++) {
            int col = n0 + tx * 8 + j;
            float v = acc[i][j] + g_bias[col];
            if (col < OUTCOLS) {
                g_OUT[((size_t)(col >> 10) * NROWS + row) * DD + (col & 1023)] = v;
            } else {
                int jj = col - OUTCOLS;
                size_t o = (size_t)row * DD + jj;
                d_inv[o] = v;                 // inv_total
                d_nxt[o] = A[o] - v;          // nxt = x - inv_total
            }
        }
    }
}

// ---------------- small vec @ Mat kernels -------------------------------------
// out[j] = sum_m vec[m]*Mat[m*ldm + j] + (addv ? addv[j] : 0)
__global__ void gemv_col(const float* __restrict__ vec, const float* __restrict__ Mat,
                         const float* __restrict__ addv, float* __restrict__ out,
                         int K, int ldm) {
    int j = blockIdx.x * blockDim.x + threadIdx.x;
    float a0 = 0.f, a1 = 0.f, a2 = 0.f, a3 = 0.f;
    for (int m = 0; m < K; m += 4) {
        a0 += vec[m + 0] * Mat[(size_t)(m + 0) * ldm + j];
        a1 += vec[m + 1] * Mat[(size_t)(m + 1) * ldm + j];
        a2 += vec[m + 2] * Mat[(size_t)(m + 2) * ldm + j];
        a3 += vec[m + 3] * Mat[(size_t)(m + 3) * ldm + j];
    }
    float acc = (a0 + a1) + (a2 + a3);
    out[j] = acc + (addv ? addv[j] : 0.f);
}

__global__ void setup_k() {
    int idx = blockIdx.x * 256 + threadIdx.x;  // 1M
    int r = idx >> 10, cc = idx & 1023;
    float m = g_Qs[idx];
    g_Nm[idx]   = (r == cc ? 1.f : 0.f) - m;   // N_1 = I - M
    g_Qsum[idx] = m;                           // Qsum = Q_1 = M
    if (idx < DD) {
        float c = g_dvec[idx];
        g_fv[idx]   = -c;                      // f_1 = -c
        g_dsum[idx] = c;                       // dsum = d_1 = c
    }
}

__global__ void update_k(int s) {
    int idx = blockIdx.x * 256 + threadIdx.x;
    float q = g_Qs[(size_t)s * DD * DD + idx];
    g_Nm[idx]   -= q;
    g_Qsum[idx] += q;
    if (idx < DD) {
        float dd = g_dvec[s * DD + idx];
        g_fv[idx]   -= dd;
        g_dsum[idx] += dd;
    }
}

__global__ void copyqsum_k() {
    int idx = blockIdx.x * 256 + threadIdx.x;
    int r = idx >> 10, j = idx & 1023;
    g_Wbig[(size_t)r * BIGN + OUTCOLS + j] = g_Qsum[idx];
}

// bias: z<NL -> e_z = d_z @ comp_W[z]^T + comp_b[z]; z==NL -> dsum
__global__ void bias_k(const float* __restrict__ comp_b) {
    int j = blockIdx.x * blockDim.x + threadIdx.x;
    int z = blockIdx.z;
    if (z == NL) { g_bias[OUTCOLS + j] = g_dsum[j]; return; }
    const float* cT = g_cT + (size_t)z * DD * DD;
    const float* dv = g_dvec + z * DD;
    float acc = 0.f;
#pragma unroll 4
    for (int m = 0; m < DD; m++) acc += dv[m] * cT[(size_t)m * DD + j];
    g_bias[z * DD + j] = acc + comp_b[z * DD + j];
}

// ---------------- loss pipeline ----------------------------------------------
__global__ void rowreduce_k() {
    int w    = blockIdx.x * (blockDim.x / 32) + (threadIdx.x >> 5);  // (i*8192 + r)
    int lane = threadIdx.x & 31;
    const float* row = g_OUT + (size_t)w * DD;
    float s = 0.f, ss = 0.f;
    for (int j = lane; j < DD; j += 32) {
        float v = row[j];
        s  += v;
        ss += v * v;
    }
#pragma unroll
    for (int o = 16; o; o >>= 1) {
        s  += __shfl_xor_sync(0xffffffffu, s,  o);
        ss += __shfl_xor_sync(0xffffffffu, ss, o);
    }
    if (!lane) { g_S[w] = s; g_n2[w] = sqrtf(ss); }
}

__global__ void loss_partial_k() {
    int j     = blockIdx.x * blockDim.x + threadIdx.x;  // column
    int chunk = blockIdx.y;                              // 0..31
    int i     = blockIdx.z;                              // 0..4
    const float* O  = g_OUT + (size_t)i * NROWS * DD;
    const float* Si = g_S  + i * NROWS;
    const float* Ni = g_n2 + i * NROWS;
    int d0 = chunk * 256;
    int d1 = d0 + 256; if (d1 > NROWS - 1) d1 = NROWS - 1;
    // c(r) = out*S / max(|out|*32*n2, 1e-8)
    float o    = O[(size_t)d0 * DD + j];
    float prev = o * Si[d0] / fmaxf(fabsf(o) * 32.0f * Ni[d0], 1e-8f);
    float acc  = 0.f;
    for (int d = d0; d < d1; d++) {
        float ov  = O[(size_t)(d + 1) * DD + j];
        float cur = ov * Si[d + 1] / fmaxf(fabsf(ov) * 32.0f * Ni[d + 1], 1e-8f);
        acc += fabsf(cur - prev);
        prev = cur;
    }
    g_Dpart[(size_t)(i * NCHUNK + chunk) * DD + j] = acc;
}

__global__ void reduceD_k() {
    int j = blockIdx.x * blockDim.x + threadIdx.x;
    float a = 0.f;
    for (int p = 0; p < NL * NCHUNK; p++) a += g_Dpart[(size_t)p * DD + j];
    g_Dv[j] = a;
}

__global__ void bcast_k(float* __restrict__ dst) {
    int idx = blockIdx.x * 256 + threadIdx.x;  // 1M
    dst[idx] = g_Dv[idx & 1023];
}

// ---------------- host orchestration -----------------------------------------
extern "C" void kernel_launch(void* const* d_in, const int* in_sizes, int n_in,
                              void* d_out, int out_size) {
    const float* x     = (const float*)d_in[0];
    const float* fc1W  = (const float*)d_in[1];
    const float* fc1b  = (const float*)d_in[2];
    const float* fc2W  = (const float*)d_in[3];
    const float* fc2b  = (const float*)d_in[4];
    const float* compW = (const float*)d_in[5];
    const float* compb = (const float*)d_in[6];

    float* out    = (float*)d_out;
    float* d_inv  = out;
    float* d_nxt  = out + (size_t)NROWS * DD;
    float* d_loss = out + 2 * (size_t)NROWS * DD;

    // device-global addresses for pointer-arg kernels
    void *vT1, *vT2, *vcT, *vQs, *vNm, *vWbig, *vdvec, *vfv;
    cudaGetSymbolAddress(&vT1, g_T1);
    cudaGetSymbolAddress(&vT2, g_T2);
    cudaGetSymbolAddress(&vcT, g_cT);
    cudaGetSymbolAddress(&vQs, g_Qs);
    cudaGetSymbolAddress(&vNm, g_Nm);
    cudaGetSymbolAddress(&vWbig, g_Wbig);
    cudaGetSymbolAddress(&vdvec, g_dvec);
    cudaGetSymbolAddress(&vfv, g_fv);
    float* pT1   = (float*)vT1;
    float* pT2   = (float*)vT2;
    float* pcT   = (float*)vcT;
    float* pQs   = (float*)vQs;
    float* pNm   = (float*)vNm;
    float* pWbig = (float*)vWbig;
    float* pdvec = (float*)vdvec;
    float* pfv   = (float*)vfv;

    dim3 tb(32, 8);

    // 1) transposes: fc1_W^T, fc2_W^T, comp_W^T (batched)
    transpose_k<<<dim3(DD / 32, HH / 32, 1), tb>>>(fc1W, pT1, HH, DD);
    transpose_k<<<dim3(HH / 32, DD / 32, 1), tb>>>(fc2W, pT2, DD, HH);
    transpose_k<<<dim3(DD / 32, DD / 32, NL), tb>>>(compW, pcT, DD, DD);

    // 2) M = fc1_W^T @ fc2_W^T  (K = 4096) -> Qs[0]
    gemm64<<<dim3(16, 16, 1), 256>>>(pT1, pT2, pQs, HH, HH, DD, DD, 0, 0, 0);

    // 3) c = fc1_b @ fc2_W^T + fc2_b  -> dvec[0]
    gemv_col<<<DD / 256, 256>>>(fc1b, pT2, fc2b, pdvec, HH, DD);

    // 4) N = I - M; Qsum = M; f = -c; dsum = c
    setup_k<<<DD * DD / 256, 256>>>();

    // 5) chain: Q_{s+1} = N_s @ M; d_{s+1} = f_s @ M + c; updates
    for (int s = 1; s < NL; s++) {
        gemm64<<<dim3(16, 16, 1), 256>>>(pNm, pQs, pQs + (size_t)s * DD * DD,
                                         DD, DD, DD, DD, 0, 0, 0);
        gemv_col<<<DD / 256, 256>>>(pfv, pQs, pdvec, pdvec + s * DD, DD, DD);
        update_k<<<DD * DD / 256, 256>>>(s);
    }

    // 6) R_z = Q_z @ comp_W[z]^T -> Wbig columns [z*1024, (z+1)*1024)
    gemm64<<<dim3(16, 16, NL), 256>>>(pQs, pcT, pWbig, DD, DD, DD, BIGN,
                                      (size_t)DD * DD, (size_t)DD * DD, (size_t)DD);
    // Wbig columns [5120,6144) = Qsum
    copyqsum_k<<<DD * DD / 256, 256>>>();

    // 7) bias: e_z and dsum
    bias_k<<<dim3(DD / 256, 1, NL + 1), 256>>>(compb);

    // 8) big fused GEMM: out_i -> g_OUT, inv_total & nxt -> d_out
    gemm_big<<<dim3(BIGN / 128, NROWS / 128), 256>>>(x, d_inv, d_nxt);

    // 9) loss: row reductions, partial column diffs, reduce, broadcast
    rowreduce_k<<<NL * NROWS / 8, 256>>>();
    loss_partial_k<<<dim3(DD / 256, NCHUNK, NL), 256>>>();
    reduceD_k<<<DD / 256, 256>>>();
    bcast_k<<<DD * DD / 256, 256>>>(d_loss);

    (void)in_sizes; (void)n_in; (void)out_size;
}

// round 16
// speedup vs baseline: 1.0025x; 1.0025x over previous
#include <cuda_runtime.h>
#include <math.h>
#include <stdint.h>

// Problem constants
#define NROWS 8192
#define DD    1024
#define HH    4096
#define NL    5          // NUM_LAYERS + 1 blocks
#define BIGN  6144       // 5*1024 (out_i) + 1024 (inv_total)
#define OUTCOLS 5120
#define NCHUNK 32        // loss row chunks

// ---------------- scratch (static device memory; no allocations) -------------
__device__ float g_T1[(size_t)DD*HH];       // fc1_W^T  [1024,4096]
__device__ float g_T2[(size_t)HH*DD];       // fc2_W^T  [4096,1024]
__device__ float g_cT[(size_t)NL*DD*DD];    // comp_W[z]^T  [m][j]
__device__ float g_Qs[(size_t)NL*DD*DD];    // Q_1..Q_5 (Qs[0] = M)
__device__ float g_Nm[(size_t)DD*DD];       // running N
__device__ float g_Qsum[(size_t)DD*DD];
__device__ float g_dvec[NL*DD];             // d_1..d_5 (dvec[0] = c)
__device__ float g_fv[DD];
__device__ float g_dsum[DD];
__device__ float g_Wbig[(size_t)DD*BIGN];
__device__ float g_bias[BIGN];
__device__ float g_OUT[(size_t)NL*NROWS*DD];  // out_i matrices (168 MB)
__device__ float g_S[NL*NROWS];
__device__ float g_n2[NL*NROWS];
__device__ float g_Dpart[NL*NCHUNK*DD];
__device__ float g_Dv[DD];

// ---------------- transpose (tiled, dims are multiples of 32) ----------------
__global__ void transpose_k(const float* __restrict__ in, float* __restrict__ out,
                            int R, int C) {
    __shared__ float tile[32][33];
    const float* ip = in  + (size_t)blockIdx.z * R * C;
    float*       op = out + (size_t)blockIdx.z * R * C;
    int x  = blockIdx.x * 32 + threadIdx.x;
    int y0 = blockIdx.y * 32 + threadIdx.y;
#pragma unroll
    for (int k = 0; k < 32; k += 8)
        tile[threadIdx.y + k][threadIdx.x] = ip[(size_t)(y0 + k) * C + x];
    __syncthreads();
    int ox  = blockIdx.y * 32 + threadIdx.x;
    int oy0 = blockIdx.x * 32 + threadIdx.y;
#pragma unroll
    for (int k = 0; k < 32; k += 8)
        op[(size_t)(oy0 + k) * R + ox] = tile[threadIdx.x][threadIdx.y + k];
}

// ---------------- small NN GEMM: 64x64 tile, BK=16, 256 thr, 4x4/thread ------
__global__ __launch_bounds__(256)
void gemm64(const float* __restrict__ A, const float* __restrict__ B,
            float* __restrict__ C, int K, int lda, int ldb, int ldc,
            size_t sA, size_t sB, size_t sC) {
    A += (size_t)blockIdx.z * sA;
    B += (size_t)blockIdx.z * sB;
    C += (size_t)blockIdx.z * sC;
    __shared__ float As[16][68];
    __shared__ float Bs[16][64];
    int t  = threadIdx.x;
    int m0 = blockIdx.y * 64, n0 = blockIdx.x * 64;
    int am = t >> 2, ak = (t & 3) * 4;
    int bk = t >> 4, bn = (t & 15) * 4;
    int ty = t >> 4, tx = t & 15;
    float acc[4][4] = {};
    const float* Aload = A + (size_t)(m0 + am) * lda + ak;
    const float* Bload = B + (size_t)bk * ldb + n0 + bn;
    for (int k0 = 0; k0 < K; k0 += 16) {
        float4 a4 = *(const float4*)(Aload + k0);
        float4 b4 = *(const float4*)(Bload + (size_t)k0 * ldb);
        __syncthreads();
        As[ak + 0][am] = a4.x; As[ak + 1][am] = a4.y;
        As[ak + 2][am] = a4.z; As[ak + 3][am] = a4.w;
        *(float4*)&Bs[bk][bn] = b4;
        __syncthreads();
#pragma unroll
        for (int k = 0; k < 16; k++) {
            float4 av = *(const float4*)&As[k][ty * 4];
            float4 bv = *(const float4*)&Bs[k][tx * 4];
            float a[4] = {av.x, av.y, av.z, av.w};
            float b[4] = {bv.x, bv.y, bv.z, bv.w};
#pragma unroll
            for (int i = 0; i < 4; i++)
#pragma unroll
                for (int j = 0; j < 4; j++)
                    acc[i][j] += a[i] * b[j];
        }
    }
#pragma unroll
    for (int i = 0; i < 4; i++) {
        float4 v = make_float4(acc[i][0], acc[i][1], acc[i][2], acc[i][3]);
        *(float4*)&C[(size_t)(m0 + ty * 4 + i) * ldc + n0 + tx * 4] = v;
    }
}

// ---------------- big GEMM: C = x @ Wbig + bias, fused routed epilogue -------
// 128x128 tile, BK=16, 256 thr, 8x8/thread
__global__ __launch_bounds__(256, 2)
void gemm_big(const float* __restrict__ A, float* __restrict__ d_inv,
              float* __restrict__ d_nxt) {
    __shared__ float As[16][132];
    __shared__ float Bs[16][128];
    int t  = threadIdx.x;
    int m0 = blockIdx.y * 128, n0 = blockIdx.x * 128;
    int ty = t >> 4, tx = t & 15;
    float acc[8][8] = {};
    for (int k0 = 0; k0 < DD; k0 += 16) {
        int f0 = t, f1 = t + 256;
        float4 a0 = *(const float4*)&A[(size_t)(m0 + (f0 >> 2)) * DD + k0 + (f0 & 3) * 4];
        float4 a1 = *(const float4*)&A[(size_t)(m0 + (f1 >> 2)) * DD + k0 + (f1 & 3) * 4];
        float4 b0 = *(const float4*)&g_Wbig[(size_t)(k0 + (f0 >> 5)) * BIGN + n0 + (f0 & 31) * 4];
        float4 b1 = *(const float4*)&g_Wbig[(size_t)(k0 + (f1 >> 5)) * BIGN + n0 + (f1 & 31) * 4];
        __syncthreads();
        {
            int am = f0 >> 2, ak = (f0 & 3) * 4;
            As[ak][am] = a0.x; As[ak + 1][am] = a0.y; As[ak + 2][am] = a0.z; As[ak + 3][am] = a0.w;
            am = f1 >> 2; ak = (f1 & 3) * 4;
            As[ak][am] = a1.x; As[ak + 1][am] = a1.y; As[ak + 2][am] = a1.z; As[ak + 3][am] = a1.w;
            *(float4*)&Bs[f0 >> 5][(f0 & 31) * 4] = b0;
            *(float4*)&Bs[f1 >> 5][(f1 & 31) * 4] = b1;
        }
        __syncthreads();
#pragma unroll
        for (int k = 0; k < 16; k++) {
            float a[8], b[8];
            *(float4*)&a[0] = *(const float4*)&As[k][ty * 8];
            *(float4*)&a[4] = *(const float4*)&As[k][ty * 8 + 4];
            *(float4*)&b[0] = *(const float4*)&Bs[k][tx * 8];
            *(float4*)&b[4] = *(const float4*)&Bs[k][tx * 8 + 4];
#pragma unroll
            for (int i = 0; i < 8; i++)
#pragma unroll
                for (int j = 0; j < 8; j++)
                    acc[i][j] += a[i] * b[j];
        }
    }
    // routed epilogue
#pragma unroll
    for (int i = 0; i < 8; i++) {
        int row = m0 + ty * 8 + i;
#pragma unroll
        for (int j = 0; j < 8; j++) {
            int col = n0 + tx * 8 + j;
            float v = acc[i][j] + g_bias[col];
            if (col < OUTCOLS) {
                g_OUT[((size_t)(col >> 10) * NROWS + row) * DD + (col & 1023)] = v;
            } else {
                int jj = col - OUTCOLS;
                size_t o = (size_t)row * DD + jj;
                d_inv[o] = v;                 // inv_total
                d_nxt[o] = A[o] - v;          // nxt = x - inv_total
            }
        }
    }
}

// ---------------- small vec @ Mat kernels -------------------------------------
// out[j] = sum_m vec[m]*Mat[m*ldm + j] + (addv ? addv[j] : 0)
__global__ void gemv_col(const float* __restrict__ vec, const float* __restrict__ Mat,
                         const float* __restrict__ addv, float* __restrict__ out,
                         int K, int ldm) {
    int j = blockIdx.x * blockDim.x + threadIdx.x;
    float a0 = 0.f, a1 = 0.f, a2 = 0.f, a3 = 0.f;
    for (int m = 0; m < K; m += 4) {
        a0 += vec[m + 0] * Mat[(size_t)(m + 0) * ldm + j];
        a1 += vec[m + 1] * Mat[(size_t)(m + 1) * ldm + j];
        a2 += vec[m + 2] * Mat[(size_t)(m + 2) * ldm + j];
        a3 += vec[m + 3] * Mat[(size_t)(m + 3) * ldm + j];
    }
    float acc = (a0 + a1) + (a2 + a3);
    out[j] = acc + (addv ? addv[j] : 0.f);
}

__global__ void setup_k() {
    int idx = blockIdx.x * 256 + threadIdx.x;  // 1M
    int r = idx >> 10, cc = idx & 1023;
    float m = g_Qs[idx];
    g_Nm[idx]   = (r == cc ? 1.f : 0.f) - m;   // N_1 = I - M
    g_Qsum[idx] = m;                           // Qsum = Q_1 = M
    if (idx < DD) {
        float c = g_dvec[idx];
        g_fv[idx]   = -c;                      // f_1 = -c
        g_dsum[idx] = c;                       // dsum = d_1 = c
    }
}

__global__ void update_k(int s) {
    int idx = blockIdx.x * 256 + threadIdx.x;
    float q = g_Qs[(size_t)s * DD * DD + idx];
    g_Nm[idx]   -= q;
    g_Qsum[idx] += q;
    if (idx < DD) {
        float dd = g_dvec[s * DD + idx];
        g_fv[idx]   -= dd;
        g_dsum[idx] += dd;
    }
}

__global__ void copyqsum_k() {
    int idx = blockIdx.x * 256 + threadIdx.x;
    int r = idx >> 10, j = idx & 1023;
    g_Wbig[(size_t)r * BIGN + OUTCOLS + j] = g_Qsum[idx];
}

// bias: z<NL -> e_z = d_z @ comp_W[z]^T + comp_b[z]; z==NL -> dsum
__global__ void bias_k(const float* __restrict__ comp_b) {
    int j = blockIdx.x * blockDim.x + threadIdx.x;
    int z = blockIdx.z;
    if (z == NL) { g_bias[OUTCOLS + j] = g_dsum[j]; return; }
    const float* cT = g_cT + (size_t)z * DD * DD;
    const float* dv = g_dvec + z * DD;
    float acc = 0.f;
#pragma unroll 4
    for (int m = 0; m < DD; m++) acc += dv[m] * cT[(size_t)m * DD + j];
    g_bias[z * DD + j] = acc + comp_b[z * DD + j];
}

// ---------------- loss pipeline ----------------------------------------------
__global__ void rowreduce_k() {
    int w    = blockIdx.x * (blockDim.x / 32) + (threadIdx.x >> 5);  // (i*8192 + r)
    int lane = threadIdx.x & 31;
    const float* row = g_OUT + (size_t)w * DD;
    float s = 0.f, ss = 0.f;
    for (int j = lane; j < DD; j += 32) {
        float v = row[j];
        s  += v;
        ss += v * v;
    }
#pragma unroll
    for (int o = 16; o; o >>= 1) {
        s  += __shfl_xor_sync(0xffffffffu, s,  o);
        ss += __shfl_xor_sync(0xffffffffu, ss, o);
    }
    if (!lane) { g_S[w] = s; g_n2[w] = sqrtf(ss); }
}

__global__ void loss_partial_k() {
    int j     = blockIdx.x * blockDim.x + threadIdx.x;  // column
    int chunk = blockIdx.y;                              // 0..31
    int i     = blockIdx.z;                              // 0..4
    const float* O  = g_OUT + (size_t)i * NROWS * DD;
    const float* Si = g_S  + i * NROWS;
    const float* Ni = g_n2 + i * NROWS;
    int d0 = chunk * 256;
    int d1 = d0 + 256; if (d1 > NROWS - 1) d1 = NROWS - 1;
    // c(r) = out*S / max(|out|*32*n2, 1e-8)
    float o    = O[(size_t)d0 * DD + j];
    float prev = o * Si[d0] / fmaxf(fabsf(o) * 32.0f * Ni[d0], 1e-8f);
    float acc  = 0.f;
    for (int d = d0; d < d1; d++) {
        float ov  = O[(size_t)(d + 1) * DD + j];
        float cur = ov * Si[d + 1] / fmaxf(fabsf(ov) * 32.0f * Ni[d + 1], 1e-8f);
        acc += fabsf(cur - prev);
        prev = cur;
    }
    g_Dpart[(size_t)(i * NCHUNK + chunk) * DD + j] = acc;
}

__global__ void reduceD_k() {
    int j = blockIdx.x * blockDim.x + threadIdx.x;
    float a = 0.f;
    for (int p = 0; p < NL * NCHUNK; p++) a += g_Dpart[(size_t)p * DD + j];
    g_Dv[j] = a;
}

__global__ void bcast_k(float* __restrict__ dst) {
    int idx = blockIdx.x * 256 + threadIdx.x;  // 1M
    dst[idx] = g_Dv[idx & 1023];
}

// ---------------- host orchestration -----------------------------------------
extern "C" void kernel_launch(void* const* d_in, const int* in_sizes, int n_in,
                              void* d_out, int out_size) {
    const float* x     = (const float*)d_in[0];
    const float* fc1W  = (const float*)d_in[1];
    const float* fc1b  = (const float*)d_in[2];
    const float* fc2W  = (const float*)d_in[3];
    const float* fc2b  = (const float*)d_in[4];
    const float* compW = (const float*)d_in[5];
    const float* compb = (const float*)d_in[6];

    float* out    = (float*)d_out;
    float* d_inv  = out;
    float* d_nxt  = out + (size_t)NROWS * DD;
    float* d_loss = out + 2 * (size_t)NROWS * DD;

    // device-global addresses for pointer-arg kernels
    void *vT1, *vT2, *vcT, *vQs, *vNm, *vWbig, *vdvec, *vfv;
    cudaGetSymbolAddress(&vT1, g_T1);
    cudaGetSymbolAddress(&vT2, g_T2);
    cudaGetSymbolAddress(&vcT, g_cT);
    cudaGetSymbolAddress(&vQs, g_Qs);
    cudaGetSymbolAddress(&vNm, g_Nm);
    cudaGetSymbolAddress(&vWbig, g_Wbig);
    cudaGetSymbolAddress(&vdvec, g_dvec);
    cudaGetSymbolAddress(&vfv, g_fv);
    float* pT1   = (float*)vT1;
    float* pT2   = (float*)vT2;
    float* pcT   = (float*)vcT;
    float* pQs   = (float*)vQs;
    float* pNm   = (float*)vNm;
    float* pWbig = (float*)vWbig;
    float* pdvec = (float*)vdvec;
    float* pfv   = (float*)vfv;

    dim3 tb(32, 8);

    // 1) transposes: fc1_W^T, fc2_W^T, comp_W^T (batched)
    transpose_k<<<dim3(DD / 32, HH / 32, 1), tb>>>(fc1W, pT1, HH, DD);
    transpose_k<<<dim3(HH / 32, DD / 32, 1), tb>>>(fc2W, pT2, DD, HH);
    transpose_k<<<dim3(DD / 32, DD / 32, NL), tb>>>(compW, pcT, DD, DD);

    // 2) M = fc1_W^T @ fc2_W^T  (K = 4096) -> Qs[0]
    gemm64<<<dim3(16, 16, 1), 256>>>(pT1, pT2, pQs, HH, HH, DD, DD, 0, 0, 0);

    // 3) c = fc1_b @ fc2_W^T + fc2_b  -> dvec[0]
    gemv_col<<<DD / 256, 256>>>(fc1b, pT2, fc2b, pdvec, HH, DD);

    // 4) N = I - M; Qsum = M; f = -c; dsum = c
    setup_k<<<DD * DD / 256, 256>>>();

    // 5) chain: Q_{s+1} = N_s @ M; d_{s+1} = f_s @ M + c; updates
    for (int s = 1; s < NL; s++) {
        gemm64<<<dim3(16, 16, 1), 256>>>(pNm, pQs, pQs + (size_t)s * DD * DD,
                                         DD, DD, DD, DD, 0, 0, 0);
        gemv_col<<<DD / 256, 256>>>(pfv, pQs, pdvec, pdvec + s * DD, DD, DD);
        update_k<<<DD * DD / 256, 256>>>(s);
    }

    // 6) R_z = Q_z @ comp_W[z]^T -> Wbig columns [z*1024, (z+1)*1024)
    gemm64<<<dim3(16, 16, NL), 256>>>(pQs, pcT, pWbig, DD, DD, DD, BIGN,
                                      (size_t)DD * DD, (size_t)DD * DD, (size_t)DD);
    // Wbig columns [5120,6144) = Qsum
    copyqsum_k<<<DD * DD / 256, 256>>>();

    // 7) bias: e_z and dsum
    bias_k<<<dim3(DD / 256, 1, NL + 1), 256>>>(compb);

    // 8) big fused GEMM: out_i -> g_OUT, inv_total & nxt -> d_out
    gemm_big<<<dim3(BIGN / 128, NROWS / 128), 256>>>(x, d_inv, d_nxt);

    // 9) loss: row reductions, partial column diffs, reduce, broadcast
    rowreduce_k<<<NL * NROWS / 8, 256>>>();
    loss_partial_k<<<dim3(DD / 256, NCHUNK, NL), 256>>>();
    reduceD_k<<<DD / 256, 256>>>();
    bcast_k<<<DD * DD / 256, 256>>>(d_loss);

    (void)in_sizes; (void)n_in; (void)out_size;
}